// round 1
// baseline (speedup 1.0000x reference)
#include <cuda_runtime.h>
#include <cuda_bf16.h>

// Gather kernel: out_means[b][d]    = mean[d][labels[b][d]]
//                out_log_vars[b][d] = log_var[d][labels[b][d]]
// B = 2097152, N_DOMAINS = 8, MAX_CONCEPTS = 64.
// d_out layout (per harness): [means (B*8 floats)] [log_vars (B*8 floats)].

#define N_DOMAINS 8
#define MAX_CONCEPTS 64
#define TAB (N_DOMAINS * MAX_CONCEPTS)   // 512 entries per table

__global__ __launch_bounds__(256, 8)
void concept_gauss_kernel(const int4* __restrict__ labels4,   // [B*2] int4 (8 ints/sample)
                          const float* __restrict__ mean,     // [8*64]
                          const float* __restrict__ log_var,  // [8*64]
                          float4* __restrict__ out4,          // [B*2] means, then [B*2] log_vars
                          int B)
{
    __shared__ float s_mean[TAB];
    __shared__ float s_var[TAB];

    // Cooperative table load: 512 entries each, 256 threads -> 2 per thread.
    int t = threadIdx.x;
    s_mean[t]       = mean[t];
    s_mean[t + 256] = mean[t + 256];
    s_var[t]        = log_var[t];
    s_var[t + 256]  = log_var[t + 256];
    __syncthreads();

    int b = blockIdx.x * blockDim.x + threadIdx.x;
    if (b >= B) return;

    // 8 labels for this sample, as two 16B loads (front-batched for MLP).
    int4 l0 = labels4[2 * b];
    int4 l1 = labels4[2 * b + 1];

    // Clamp not needed (labels in [0,64)), direct smem gathers.
    float m0 = s_mean[0 * MAX_CONCEPTS + l0.x];
    float m1 = s_mean[1 * MAX_CONCEPTS + l0.y];
    float m2 = s_mean[2 * MAX_CONCEPTS + l0.z];
    float m3 = s_mean[3 * MAX_CONCEPTS + l0.w];
    float m4 = s_mean[4 * MAX_CONCEPTS + l1.x];
    float m5 = s_mean[5 * MAX_CONCEPTS + l1.y];
    float m6 = s_mean[6 * MAX_CONCEPTS + l1.z];
    float m7 = s_mean[7 * MAX_CONCEPTS + l1.w];

    float v0 = s_var[0 * MAX_CONCEPTS + l0.x];
    float v1 = s_var[1 * MAX_CONCEPTS + l0.y];
    float v2 = s_var[2 * MAX_CONCEPTS + l0.z];
    float v3 = s_var[3 * MAX_CONCEPTS + l0.w];
    float v4 = s_var[4 * MAX_CONCEPTS + l1.x];
    float v5 = s_var[5 * MAX_CONCEPTS + l1.y];
    float v6 = s_var[6 * MAX_CONCEPTS + l1.z];
    float v7 = s_var[7 * MAX_CONCEPTS + l1.w];

    // Coalesced 16B stores. means at [0, 2B), log_vars at [2B, 4B) in float4 units.
    out4[2 * b]             = make_float4(m0, m1, m2, m3);
    out4[2 * b + 1]         = make_float4(m4, m5, m6, m7);
    long vbase = 2L * B;
    out4[vbase + 2 * b]     = make_float4(v0, v1, v2, v3);
    out4[vbase + 2 * b + 1] = make_float4(v4, v5, v6, v7);
}

extern "C" void kernel_launch(void* const* d_in, const int* in_sizes, int n_in,
                              void* d_out, int out_size) {
    const int4*  labels4 = (const int4*)d_in[0];
    const float* mean    = (const float*)d_in[1];
    const float* log_var = (const float*)d_in[2];
    float4* out4 = (float4*)d_out;

    int B = in_sizes[0] / N_DOMAINS;   // 2097152
    int threads = 256;
    int blocks = (B + threads - 1) / threads;
    concept_gauss_kernel<<<blocks, threads>>>(labels4, mean, log_var, out4, B);
}